// round 14
// baseline (speedup 1.0000x reference)
#include <cuda_runtime.h>
#include <cuda_fp16.h>
#include <cstdint>

#define NTOK 8192
#define DIM  2048
#define NEXP 8
#define TOPK 2

#define BM 128
#define BN 128
#define BK 64                          // halves per k-iter
#define STAGES 3
#define KITERS (DIM / BK)              // 32
#define NUNITS_N (DIM / BN)            // 16 n-slices per row-tile

#define PERSIST_CTAS 296               // 148 SMs x 2 CTAs

#define STAGE_BYTES (BM * BK * 2)      // 16384
#define SMEM_TOTAL  (2 * STAGES * STAGE_BYTES)  // 98304

#define GATE_BLOCKS 1024               // 8 warps/block, 1 token/warp
#define CONV_BLOCKS 2048               // W-convert + out-zero slices
#define PREP_BLOCKS (GATE_BLOCKS + CONV_BLOCKS)

// ---------------- device globals ----------------
__device__ int    g_count[NEXP];
__device__ int    g_tok[NEXP * NTOK];
__device__ float  g_wt [NEXP * NTOK];
__device__ __half g_xh[(size_t)NEXP * NTOK * DIM];   // per-expert padded fp16 A
__device__ __half g_wh[(size_t)NEXP * DIM * DIM];    // fp16 W

// ---------------- helpers ----------------
__device__ __forceinline__ uint32_t smem_u32(const void* p) {
    uint32_t a;
    asm("{ .reg .u64 t; cvta.to.shared.u64 t, %1; cvt.u32.u64 %0, t; }" : "=r"(a) : "l"(p));
    return a;
}
#define CP16(dst, src) \
    asm volatile("cp.async.cg.shared.global [%0], [%1], 16;" :: "r"(dst), "l"(src) : "memory")
#define CP_COMMIT() asm volatile("cp.async.commit_group;" ::: "memory")
#define CP_WAIT1()  asm volatile("cp.async.wait_group 1;" ::: "memory")
#define CP_WAIT0()  asm volatile("cp.async.wait_group 0;" ::: "memory")

#define LDSM4(r0, r1, r2, r3, addr) \
    asm volatile("ldmatrix.sync.aligned.m8n8.x4.shared.b16 {%0,%1,%2,%3}, [%4];" \
        : "=r"(r0), "=r"(r1), "=r"(r2), "=r"(r3) : "r"(addr))

__device__ __forceinline__ void mma_f16(float* d, const uint32_t* a, const uint32_t* b) {
    asm volatile(
        "mma.sync.aligned.m16n8k16.row.col.f32.f16.f16.f32 "
        "{%0,%1,%2,%3}, {%4,%5,%6,%7}, {%8,%9}, {%0,%1,%2,%3};"
        : "+f"(d[0]), "+f"(d[1]), "+f"(d[2]), "+f"(d[3])
        : "r"(a[0]), "r"(a[1]), "r"(a[2]), "r"(a[3]), "r"(b[0]), "r"(b[1]));
}

// ---------------- kernel 0: init counters ----------------
__global__ void init_kernel() {
    if (threadIdx.x < NEXP) g_count[threadIdx.x] = 0;
}

// ---------------- kernel 1: fused prep ----------------
__global__ void __launch_bounds__(256)
prep_kernel(const float* __restrict__ x,
            const float4* __restrict__ W,
            const float* __restrict__ Wg,
            const float* __restrict__ bg,
            float4* __restrict__ out) {
    int bid = blockIdx.x;
    int tid = threadIdx.x;

    if (bid >= GATE_BLOCKS) {
        int cid = bid - GATE_BLOCKS;
        {
            __half2* dst = (__half2*)g_wh;
            size_t base = (size_t)cid * 4096 + tid;
#pragma unroll 4
            for (int i = 0; i < 16; i++) {
                size_t idx = base + (size_t)i * 256;
                float4 v = W[idx];
                dst[2 * idx]     = __floats2half2_rn(v.x, v.y);
                dst[2 * idx + 1] = __floats2half2_rn(v.z, v.w);
            }
        }
        {
            float4 z = make_float4(0.f, 0.f, 0.f, 0.f);
            size_t base = (size_t)cid * 2048 + tid;
#pragma unroll
            for (int i = 0; i < 8; i++)
                out[base + (size_t)i * 256] = z;
        }
        return;
    }

    int wid  = tid >> 5;
    int lane = tid & 31;
    int tok  = bid * 8 + wid;

    const float* xr = x + (size_t)tok * DIM;
    float acc[NEXP];
#pragma unroll
    for (int e = 0; e < NEXP; e++) acc[e] = 0.f;
    for (int i = lane; i < DIM; i += 32) {
        float xv = xr[i];
#pragma unroll
        for (int e = 0; e < NEXP; e++)
            acc[e] = fmaf(xv, Wg[e * DIM + i], acc[e]);
    }
#pragma unroll
    for (int off = 16; off; off >>= 1)
#pragma unroll
        for (int e = 0; e < NEXP; e++)
            acc[e] += __shfl_xor_sync(0xffffffffu, acc[e], off);

    int i0 = 0, i1 = 0, p0 = 0, p1 = 0;
    if (lane == 0) {
        float m = -3.4e38f;
#pragma unroll
        for (int e = 0; e < NEXP; e++) { acc[e] += bg[e]; m = fmaxf(m, acc[e]); }
        float p[NEXP], s = 0.f;
#pragma unroll
        for (int e = 0; e < NEXP; e++) { p[e] = expf(acc[e] - m); s += p[e]; }
        i0 = 0;
#pragma unroll
        for (int e = 1; e < NEXP; e++) if (p[e] > p[i0]) i0 = e;
        i1 = (i0 == 0) ? 1 : 0;
#pragma unroll
        for (int e = 0; e < NEXP; e++)
            if (e != i0 && p[e] > p[i1]) i1 = e;

        float inv = 1.f / s;
        p0 = atomicAdd(&g_count[i0], 1);
        p1 = atomicAdd(&g_count[i1], 1);
        g_tok[i0 * NTOK + p0] = tok;  g_wt[i0 * NTOK + p0] = p[i0] * inv;
        g_tok[i1 * NTOK + p1] = tok;  g_wt[i1 * NTOK + p1] = p[i1] * inv;
    }
    i0 = __shfl_sync(0xffffffffu, i0, 0);
    i1 = __shfl_sync(0xffffffffu, i1, 0);
    p0 = __shfl_sync(0xffffffffu, p0, 0);
    p1 = __shfl_sync(0xffffffffu, p1, 0);

    const float4* src = (const float4*)xr;
    __half2* d0 = (__half2*)(g_xh + ((size_t)i0 * NTOK + p0) * DIM);
    __half2* d1 = (__half2*)(g_xh + ((size_t)i1 * NTOK + p1) * DIM);
    for (int i = lane; i < DIM / 4; i += 32) {
        float4 v = src[i];
        __half2 h0 = __floats2half2_rn(v.x, v.y);
        __half2 h1 = __floats2half2_rn(v.z, v.w);
        d0[2 * i] = h0; d0[2 * i + 1] = h1;
        d1[2 * i] = h0; d1[2 * i + 1] = h1;
    }
}

// ---------------- kernel 2: persistent FP16 mma.sync grouped GEMM ----------
// 296 persistent CTAs loop over work units (row-tile x n-slice).  Mainloop
// is the proven R9 structure (32x64 warp tile, A double-buffer, B JIT
// rotation, 3-stage cp.async, 1 barrier/k-tile).  At unit end the next
// unit's stage-0/1 loads are issued BEFORE the epilogue, hiding pipeline
// fill under the RED.F32 tail and removing wave quantization.
__global__ void __launch_bounds__(256, 2)
moe_mma_gemm(const float* __restrict__ bias, float* __restrict__ out) {
    // total units
    int ntiles = 0;
#pragma unroll
    for (int i = 0; i < NEXP; i++) ntiles += (g_count[i] + BM - 1) >> 7;
    int nunits = ntiles * NUNITS_N;

    int u = blockIdx.x;
    if (u >= nunits) return;

    extern __shared__ char smem[];
    uint32_t sbase = smem_u32(smem);

    int tid    = threadIdx.x;
    int lane   = tid & 31;
    int wid    = tid >> 5;
    int warp_m = wid & 3;
    int warp_n = wid >> 2;
    int fr     = lane >> 2;
    int fc     = lane & 3;

    int lrow = tid >> 1;
    int cgrp = (tid & 1) * 4;
    uint32_t rowOff = lrow * 128;
    int      rSw    = lrow & 7;

    int mi  = lane >> 3;
    int r8  = lane & 7;
    int aCh = mi >> 1;
    uint32_t aBase[2];
    int      aSw[2];
#pragma unroll
    for (int tm = 0; tm < 2; tm++) {
        int r = warp_m * 32 + tm * 16 + (mi & 1) * 8 + r8;
        aBase[tm] = r * 128;
        aSw[tm]   = r & 7;
    }
    int bCh = mi & 1;
    uint32_t bBase[4];
    int      bSw[4];
#pragma unroll
    for (int p = 0; p < 4; p++) {
        int r = warp_n * 64 + (2 * p + (mi >> 1)) * 8 + r8;
        bBase[p] = r * 128;
        bSw[p]   = r & 7;
    }

    // unit -> (e, r0, n0) resolution (g_count reads are L1-hot)
    int e = 0, r0 = 0, n0 = 0;
    auto resolve = [&](int uu) {
        int tile = uu >> 4;
        n0 = (uu & 15) * BN;
        int at = 0;
#pragma unroll
        for (int i = 0; i < NEXP; i++) {
            int t = (g_count[i] + BM - 1) >> 7;
            if (tile >= at && tile < at + t) { e = i; r0 = (tile - at) * BM; }
            at += t;
        }
    };

    const __half* gA;
    const __half* gB;
    auto set_ptrs = [&]() {
        gA = g_xh + ((size_t)e * NTOK + r0 + lrow) * DIM + cgrp * 8;
        gB = g_wh + ((size_t)e * DIM + n0 + lrow) * DIM + cgrp * 8;
    };

    auto load_stage = [&](int s, int kt) {
        uint32_t da = sbase + s * STAGE_BYTES + rowOff;
        uint32_t db = sbase + (STAGES + s) * STAGE_BYTES + rowOff;
        const __half* pa = gA + kt * BK;
        const __half* pb = gB + kt * BK;
#pragma unroll
        for (int c = 0; c < 4; c++) {
            uint32_t pc = (uint32_t)((cgrp + c) ^ rSw) << 4;
            CP16(da + pc, pa + c * 8);
            CP16(db + pc, pb + c * 8);
        }
        CP_COMMIT();
    };

    uint32_t a[2][2][4], b[2][4];
    auto load_a = [&](int buf, int kk, uint32_t As) {
#pragma unroll
        for (int tm = 0; tm < 2; tm++) {
            uint32_t addr = As + aBase[tm] +
                            ((uint32_t)((kk * 2 + aCh) ^ aSw[tm]) << 4);
            LDSM4(a[buf][tm][0], a[buf][tm][1], a[buf][tm][2], a[buf][tm][3], addr);
        }
    };
    auto load_b = [&](int buf, int kk, int p, uint32_t Bs) {
        uint32_t addr = Bs + bBase[p] +
                        ((uint32_t)((kk * 2 + bCh) ^ bSw[p]) << 4);
        LDSM4(b[buf][0], b[buf][1], b[buf][2], b[buf][3], addr);
    };

    // first unit prologue
    resolve(u);
    set_ptrs();
    load_stage(0, 0);
    load_stage(1, 1);

    while (true) {
        float acc[2][8][4];
#pragma unroll
        for (int i = 0; i < 2; i++)
#pragma unroll
            for (int j = 0; j < 8; j++)
#pragma unroll
                for (int k = 0; k < 4; k++) acc[i][j][k] = 0.f;

#pragma unroll 1
        for (int kt = 0; kt < KITERS; kt++) {
            if (kt < KITERS - 1) { CP_WAIT1(); } else { CP_WAIT0(); }
            __syncthreads();   // stage kt visible to all; prior reads done

            uint32_t As = sbase + (kt % STAGES) * STAGE_BYTES;
            uint32_t Bs = sbase + (STAGES + (kt % STAGES)) * STAGE_BYTES;

            load_a(0, 0, As);
            load_b(0, 0, 0, Bs);

            int kp = kt + STAGES - 1;
            if (kp < KITERS) load_stage(kp % STAGES, kp);

#pragma unroll
            for (int j = 0; j < BK / 16; j++) {
                int cur = j & 1;
                if (j < BK / 16 - 1) load_a(cur ^ 1, j + 1, As);
#pragma unroll
                for (int p = 0; p < 4; p++) {
                    int pb = p & 1;
                    if (p < 3)                load_b(pb ^ 1, j,     p + 1, Bs);
                    else if (j < BK / 16 - 1) load_b(pb ^ 1, j + 1, 0,     Bs);
#pragma unroll
                    for (int tm = 0; tm < 2; tm++) {
                        mma_f16(acc[tm][2 * p],     a[cur][tm], &b[pb][0]);
                        mma_f16(acc[tm][2 * p + 1], a[cur][tm], &b[pb][2]);
                    }
                }
            }
        }

        // capture current unit coords for the epilogue
        int cur_e = e, cur_r0 = r0, cur_n0 = n0;
        int cnt = g_count[cur_e];

        // advance; issue next unit's first stages BEFORE epilogue
        u += gridDim.x;
        bool more = (u < nunits);
        __syncthreads();          // all smem reads of this unit complete
        if (more) {
            resolve(u);
            set_ptrs();
            load_stage(0, 0);     // overlaps with epilogue below
            load_stage(1, 1);
        }

        // epilogue: bias + relu + gate weight -> atomicAdd into out
        int c2 = 2 * fc;
        float2 bv[8];
#pragma unroll
        for (int tn = 0; tn < 8; tn++) {
            const float* bp = bias + (size_t)cur_e * DIM + cur_n0 + warp_n * 64 + tn * 8 + c2;
            bv[tn] = make_float2(__ldg(bp), __ldg(bp + 1));
        }
#pragma unroll
        for (int tm = 0; tm < 2; tm++) {
#pragma unroll
            for (int half = 0; half < 2; half++) {
                int row = warp_m * 32 + tm * 16 + half * 8 + fr;
                int idx = cur_r0 + row;
                if (idx >= cnt) continue;
                int   tok = g_tok[cur_e * NTOK + idx];
                float wgt = g_wt [cur_e * NTOK + idx];
                float* orow = out + (size_t)tok * DIM + cur_n0 + warp_n * 64;
#pragma unroll
                for (int tn = 0; tn < 8; tn++) {
                    float v0 = fmaxf(acc[tm][tn][half * 2 + 0] + bv[tn].x, 0.f) * wgt;
                    float v1 = fmaxf(acc[tm][tn][half * 2 + 1] + bv[tn].y, 0.f) * wgt;
                    atomicAdd(orow + tn * 8 + c2,     v0);
                    atomicAdd(orow + tn * 8 + c2 + 1, v1);
                }
            }
        }

        if (!more) break;
    }
}

// ---------------- launch ----------------
extern "C" void kernel_launch(void* const* d_in, const int* in_sizes, int n_in,
                              void* d_out, int out_size) {
    const float* x  = (const float*)d_in[0];
    const float* W  = (const float*)d_in[1];
    const float* b  = (const float*)d_in[2];
    const float* Wg = (const float*)d_in[3];
    const float* bg = (const float*)d_in[4];
    float* out = (float*)d_out;
    (void)in_sizes; (void)n_in; (void)out_size;

    cudaFuncSetAttribute(moe_mma_gemm, cudaFuncAttributeMaxDynamicSharedMemorySize, SMEM_TOTAL);

    init_kernel<<<1, 32>>>();
    prep_kernel<<<PREP_BLOCKS, 256>>>(x, (const float4*)W, Wg, bg, (float4*)out);
    moe_mma_gemm<<<PERSIST_CTAS, 256, SMEM_TOTAL>>>(b, out);
}

// round 15
// speedup vs baseline: 1.0540x; 1.0540x over previous
#include <cuda_runtime.h>
#include <cuda_fp16.h>
#include <cstdint>

#define NTOK 8192
#define DIM  2048
#define NEXP 8
#define TOPK 2

#define BM 128
#define BN 128
#define BK 64                          // halves per k-iter
#define STAGES 3
#define KITERS (DIM / BK)              // 32
#define NSLICES (DIM / BN)             // 16

#define MAXTILES 136

#define STAGE_BYTES (BM * BK * 2)      // 16384
#define SMEM_TOTAL  (2 * STAGES * STAGE_BYTES)  // 98304

#define GATE_BLOCKS 1024               // 8 warps/block, 1 token/warp
#define CONV_BLOCKS 2048               // W-convert + out-zero slices
#define PREP_BLOCKS (GATE_BLOCKS + CONV_BLOCKS)

// ---------------- device globals ----------------
__device__ int    g_count[NEXP];
__device__ int    g_tok[NEXP * NTOK];
__device__ float  g_wt [NEXP * NTOK];
__device__ __half g_xh[(size_t)NTOK * DIM];          // fp16 x, token order (single copy)
__device__ __half g_wh[(size_t)NEXP * DIM * DIM];    // fp16 W

// ---------------- helpers ----------------
__device__ __forceinline__ uint32_t smem_u32(const void* p) {
    uint32_t a;
    asm("{ .reg .u64 t; cvta.to.shared.u64 t, %1; cvt.u32.u64 %0, t; }" : "=r"(a) : "l"(p));
    return a;
}
#define CP16(dst, src) \
    asm volatile("cp.async.cg.shared.global [%0], [%1], 16;" :: "r"(dst), "l"(src) : "memory")
#define CP_COMMIT() asm volatile("cp.async.commit_group;" ::: "memory")
#define CP_WAIT1()  asm volatile("cp.async.wait_group 1;" ::: "memory")
#define CP_WAIT0()  asm volatile("cp.async.wait_group 0;" ::: "memory")

#define LDSM4(r0, r1, r2, r3, addr) \
    asm volatile("ldmatrix.sync.aligned.m8n8.x4.shared.b16 {%0,%1,%2,%3}, [%4];" \
        : "=r"(r0), "=r"(r1), "=r"(r2), "=r"(r3) : "r"(addr))

__device__ __forceinline__ void mma_f16(float* d, const uint32_t* a, const uint32_t* b) {
    asm volatile(
        "mma.sync.aligned.m16n8k16.row.col.f32.f16.f16.f32 "
        "{%0,%1,%2,%3}, {%4,%5,%6,%7}, {%8,%9}, {%0,%1,%2,%3};"
        : "+f"(d[0]), "+f"(d[1]), "+f"(d[2]), "+f"(d[3])
        : "r"(a[0]), "r"(a[1]), "r"(a[2]), "r"(a[3]), "r"(b[0]), "r"(b[1]));
}

// ---------------- kernel 0: init counters ----------------
__global__ void init_kernel() {
    if (threadIdx.x < NEXP) g_count[threadIdx.x] = 0;
}

// ---------------- kernel 1: fused prep ----------------
// gate blocks: gating + single linear fp16 convert of the token row.
// conv blocks: W fp32->fp16 slice + out-zero slice.
__global__ void __launch_bounds__(256)
prep_kernel(const float* __restrict__ x,
            const float4* __restrict__ W,
            const float* __restrict__ Wg,
            const float* __restrict__ bg,
            float4* __restrict__ out) {
    int bid = blockIdx.x;
    int tid = threadIdx.x;

    if (bid >= GATE_BLOCKS) {
        int cid = bid - GATE_BLOCKS;
        {
            __half2* dst = (__half2*)g_wh;
            size_t base = (size_t)cid * 4096 + tid;
#pragma unroll 4
            for (int i = 0; i < 16; i++) {
                size_t idx = base + (size_t)i * 256;
                float4 v = W[idx];
                dst[2 * idx]     = __floats2half2_rn(v.x, v.y);
                dst[2 * idx + 1] = __floats2half2_rn(v.z, v.w);
            }
        }
        {
            float4 z = make_float4(0.f, 0.f, 0.f, 0.f);
            size_t base = (size_t)cid * 2048 + tid;
#pragma unroll
            for (int i = 0; i < 8; i++)
                out[base + (size_t)i * 256] = z;
        }
        return;
    }

    int wid  = tid >> 5;
    int lane = tid & 31;
    int tok  = bid * 8 + wid;

    const float* xr = x + (size_t)tok * DIM;
    float acc[NEXP];
#pragma unroll
    for (int e = 0; e < NEXP; e++) acc[e] = 0.f;
    for (int i = lane; i < DIM; i += 32) {
        float xv = xr[i];
#pragma unroll
        for (int e = 0; e < NEXP; e++)
            acc[e] = fmaf(xv, Wg[e * DIM + i], acc[e]);
    }
#pragma unroll
    for (int off = 16; off; off >>= 1)
#pragma unroll
        for (int e = 0; e < NEXP; e++)
            acc[e] += __shfl_xor_sync(0xffffffffu, acc[e], off);

    if (lane == 0) {
        float m = -3.4e38f;
#pragma unroll
        for (int e = 0; e < NEXP; e++) { acc[e] += bg[e]; m = fmaxf(m, acc[e]); }
        float p[NEXP], s = 0.f;
#pragma unroll
        for (int e = 0; e < NEXP; e++) { p[e] = expf(acc[e] - m); s += p[e]; }
        int i0 = 0;
#pragma unroll
        for (int e = 1; e < NEXP; e++) if (p[e] > p[i0]) i0 = e;
        int i1 = (i0 == 0) ? 1 : 0;
#pragma unroll
        for (int e = 0; e < NEXP; e++)
            if (e != i0 && p[e] > p[i1]) i1 = e;

        float inv = 1.f / s;
        int p0 = atomicAdd(&g_count[i0], 1);
        int p1 = atomicAdd(&g_count[i1], 1);
        g_tok[i0 * NTOK + p0] = tok;  g_wt[i0 * NTOK + p0] = p[i0] * inv;
        g_tok[i1 * NTOK + p1] = tok;  g_wt[i1 * NTOK + p1] = p[i1] * inv;
    }

    // single linear fp16 copy of this token's row (no per-expert scatter)
    const float4* src = (const float4*)xr;
    __half2* dst = (__half2*)(g_xh + (size_t)tok * DIM);
    for (int i = lane; i < DIM / 4; i += 32) {
        float4 v = src[i];
        dst[2 * i]     = __floats2half2_rn(v.x, v.y);
        dst[2 * i + 1] = __floats2half2_rn(v.z, v.w);
    }
}

// ---------------- kernel 2: FP16 mma.sync grouped GEMM (R9 mainloop) ------
// grid(x = 16 n-slices, y = row-tiles): x varies fastest, so concurrent
// CTAs share row-tiles/experts -> A, B, out all L2-resident.
// A rows gathered from token-order g_xh via g_tok (cp.async per-row ptr).
__global__ void __launch_bounds__(256, 2)
moe_mma_gemm(const float* __restrict__ bias, float* __restrict__ out) {
    int tile = blockIdx.y;
    int n0   = blockIdx.x * BN;

    // derive (expert, row-tile) from counts
    int e = -1, r0 = 0, nt = 0;
#pragma unroll
    for (int i = 0; i < NEXP; i++) {
        int t = (g_count[i] + BM - 1) >> 7;
        if (e < 0 && tile < nt + t) { e = i; r0 = (tile - nt) * BM; }
        nt += t;
    }
    if (e < 0) return;
    int cnt = g_count[e];

    extern __shared__ char smem[];
    uint32_t sbase = smem_u32(smem);

    int tid    = threadIdx.x;
    int lane   = tid & 31;
    int wid    = tid >> 5;
    int warp_m = wid & 3;
    int warp_n = wid >> 2;
    int fr     = lane >> 2;
    int fc     = lane & 3;

    int lrow = tid >> 1;
    int cgrp = (tid & 1) * 4;
    // gather: row lrow of this tile -> token row in g_xh (clamp pad rows)
    int arow = r0 + lrow; if (arow >= cnt) arow = cnt - 1;
    int atok = g_tok[e * NTOK + arow];
    const __half* gA = g_xh + (size_t)atok * DIM + cgrp * 8;
    const __half* gB = g_wh + ((size_t)e * DIM + n0 + lrow) * DIM + cgrp * 8;
    uint32_t rowOff = lrow * 128;
    int      rSw    = lrow & 7;

    int mi  = lane >> 3;
    int r8  = lane & 7;
    int aCh = mi >> 1;
    uint32_t aBase[2];
    int      aSw[2];
#pragma unroll
    for (int tm = 0; tm < 2; tm++) {
        int r = warp_m * 32 + tm * 16 + (mi & 1) * 8 + r8;
        aBase[tm] = r * 128;
        aSw[tm]   = r & 7;
    }
    int bCh = mi & 1;
    uint32_t bBase[4];
    int      bSw[4];
#pragma unroll
    for (int p = 0; p < 4; p++) {
        int r = warp_n * 64 + (2 * p + (mi >> 1)) * 8 + r8;
        bBase[p] = r * 128;
        bSw[p]   = r & 7;
    }

    float acc[2][8][4];
#pragma unroll
    for (int i = 0; i < 2; i++)
#pragma unroll
        for (int j = 0; j < 8; j++)
#pragma unroll
            for (int k = 0; k < 4; k++) acc[i][j][k] = 0.f;

    auto load_stage = [&](int s, int kt) {
        uint32_t da = sbase + s * STAGE_BYTES + rowOff;
        uint32_t db = sbase + (STAGES + s) * STAGE_BYTES + rowOff;
        const __half* pa = gA + kt * BK;
        const __half* pb = gB + kt * BK;
#pragma unroll
        for (int c = 0; c < 4; c++) {
            uint32_t pc = (uint32_t)((cgrp + c) ^ rSw) << 4;
            CP16(da + pc, pa + c * 8);
            CP16(db + pc, pb + c * 8);
        }
        CP_COMMIT();
    };

    // fragment buffers: A double (per k16 step), B 2-slot pair rotation
    uint32_t a[2][2][4], b[2][4];

    auto load_a = [&](int buf, int kk, uint32_t As) {
#pragma unroll
        for (int tm = 0; tm < 2; tm++) {
            uint32_t addr = As + aBase[tm] +
                            ((uint32_t)((kk * 2 + aCh) ^ aSw[tm]) << 4);
            LDSM4(a[buf][tm][0], a[buf][tm][1], a[buf][tm][2], a[buf][tm][3], addr);
        }
    };
    auto load_b = [&](int buf, int kk, int p, uint32_t Bs) {
        uint32_t addr = Bs + bBase[p] +
                        ((uint32_t)((kk * 2 + bCh) ^ bSw[p]) << 4);
        LDSM4(b[buf][0], b[buf][1], b[buf][2], b[buf][3], addr);
    };

#pragma unroll
    for (int s = 0; s < STAGES - 1; s++) load_stage(s, s);

#pragma unroll 1
    for (int kt = 0; kt < KITERS; kt++) {
        if (kt < KITERS - 1) { CP_WAIT1(); } else { CP_WAIT0(); }
        __syncthreads();   // prior-iter reads done; stage kt resident

        uint32_t As = sbase + (kt % STAGES) * STAGE_BYTES;
        uint32_t Bs = sbase + (STAGES + (kt % STAGES)) * STAGE_BYTES;

        load_a(0, 0, As);
        load_b(0, 0, 0, Bs);

        int kp = kt + STAGES - 1;
        if (kp < KITERS) load_stage(kp % STAGES, kp);

#pragma unroll
        for (int j = 0; j < BK / 16; j++) {
            int cur = j & 1;
            if (j < BK / 16 - 1) load_a(cur ^ 1, j + 1, As);
#pragma unroll
            for (int p = 0; p < 4; p++) {
                int pb = p & 1;
                if (p < 3)                load_b(pb ^ 1, j,     p + 1, Bs);
                else if (j < BK / 16 - 1) load_b(pb ^ 1, j + 1, 0,     Bs);
#pragma unroll
                for (int tm = 0; tm < 2; tm++) {
                    mma_f16(acc[tm][2 * p],     a[cur][tm], &b[pb][0]);
                    mma_f16(acc[tm][2 * p + 1], a[cur][tm], &b[pb][2]);
                }
            }
        }
    }

    // epilogue: bias + relu + gate weight -> atomicAdd into out
    int c2 = 2 * fc;
    float2 bv[8];
#pragma unroll
    for (int tn = 0; tn < 8; tn++) {
        const float* bp = bias + (size_t)e * DIM + n0 + warp_n * 64 + tn * 8 + c2;
        bv[tn] = make_float2(__ldg(bp), __ldg(bp + 1));
    }
#pragma unroll
    for (int tm = 0; tm < 2; tm++) {
#pragma unroll
        for (int half = 0; half < 2; half++) {
            int row = warp_m * 32 + tm * 16 + half * 8 + fr;
            int idx = r0 + row;
            if (idx >= cnt) continue;
            int   tok = g_tok[e * NTOK + idx];
            float wgt = g_wt [e * NTOK + idx];
            float* orow = out + (size_t)tok * DIM + n0 + warp_n * 64;
#pragma unroll
            for (int tn = 0; tn < 8; tn++) {
                float v0 = fmaxf(acc[tm][tn][half * 2 + 0] + bv[tn].x, 0.f) * wgt;
                float v1 = fmaxf(acc[tm][tn][half * 2 + 1] + bv[tn].y, 0.f) * wgt;
                atomicAdd(orow + tn * 8 + c2,     v0);
                atomicAdd(orow + tn * 8 + c2 + 1, v1);
            }
        }
    }
}

// ---------------- launch ----------------
extern "C" void kernel_launch(void* const* d_in, const int* in_sizes, int n_in,
                              void* d_out, int out_size) {
    const float* x  = (const float*)d_in[0];
    const float* W  = (const float*)d_in[1];
    const float* b  = (const float*)d_in[2];
    const float* Wg = (const float*)d_in[3];
    const float* bg = (const float*)d_in[4];
    float* out = (float*)d_out;
    (void)in_sizes; (void)n_in; (void)out_size;

    cudaFuncSetAttribute(moe_mma_gemm, cudaFuncAttributeMaxDynamicSharedMemorySize, SMEM_TOTAL);

    init_kernel<<<1, 32>>>();
    prep_kernel<<<PREP_BLOCKS, 256>>>(x, (const float4*)W, Wg, bg, (float4*)out);
    moe_mma_gemm<<<dim3(NSLICES, MAXTILES), 256, SMEM_TOTAL>>>(b, out);
}

// round 16
// speedup vs baseline: 1.0774x; 1.0222x over previous
#include <cuda_runtime.h>
#include <cuda_fp16.h>
#include <cstdint>

#define NTOK 8192
#define DIM  2048
#define NEXP 8
#define TOPK 2

#define BM 128
#define BN 128
#define BK 64                          // halves per k-iter
#define STAGES 3
#define KITERS (DIM / BK)              // 32

#define GRID_ROWTILES 136

#define STAGE_BYTES (BM * BK * 2)      // 16384
#define SMEM_TOTAL  (2 * STAGES * STAGE_BYTES)  // 98304

#define GATE_BLOCKS 1024               // 8 warps/block, 1 token/warp
#define CONV_BLOCKS 4096               // W-convert + out-zero slices
#define PREP_BLOCKS (GATE_BLOCKS + CONV_BLOCKS)

// ---------------- device globals ----------------
__device__ int    g_count[NEXP];
__device__ int    g_tok[NEXP * NTOK];
__device__ float  g_wt [NEXP * NTOK];
__device__ __half g_xh[(size_t)NEXP * NTOK * DIM];   // per-expert padded fp16 A
__device__ __half g_wh[(size_t)NEXP * DIM * DIM];    // fp16 W

// ---------------- helpers ----------------
__device__ __forceinline__ uint32_t smem_u32(const void* p) {
    uint32_t a;
    asm("{ .reg .u64 t; cvta.to.shared.u64 t, %1; cvt.u32.u64 %0, t; }" : "=r"(a) : "l"(p));
    return a;
}
#define CP16(dst, src) \
    asm volatile("cp.async.cg.shared.global [%0], [%1], 16;" :: "r"(dst), "l"(src) : "memory")
#define CP_COMMIT() asm volatile("cp.async.commit_group;" ::: "memory")
#define CP_WAIT1()  asm volatile("cp.async.wait_group 1;" ::: "memory")
#define CP_WAIT0()  asm volatile("cp.async.wait_group 0;" ::: "memory")

#define LDSM4(r0, r1, r2, r3, addr) \
    asm volatile("ldmatrix.sync.aligned.m8n8.x4.shared.b16 {%0,%1,%2,%3}, [%4];" \
        : "=r"(r0), "=r"(r1), "=r"(r2), "=r"(r3) : "r"(addr))

__device__ __forceinline__ void mma_f16(float* d, const uint32_t* a, const uint32_t* b) {
    asm volatile(
        "mma.sync.aligned.m16n8k16.row.col.f32.f16.f16.f32 "
        "{%0,%1,%2,%3}, {%4,%5,%6,%7}, {%8,%9}, {%0,%1,%2,%3};"
        : "+f"(d[0]), "+f"(d[1]), "+f"(d[2]), "+f"(d[3])
        : "r"(a[0]), "r"(a[1]), "r"(a[2]), "r"(a[3]), "r"(b[0]), "r"(b[1]));
}

__device__ __forceinline__ uint32_t pack_h2(float x, float y) {
    __half2 h = __floats2half2_rn(x, y);
    return *(uint32_t*)&h;
}

// ---------------- kernel 0: init counters ----------------
__global__ void init_kernel() {
    if (threadIdx.x < NEXP) g_count[threadIdx.x] = 0;
}

// ---------------- kernel 1: fused prep ----------------
// gate blocks: gating (1 warp/token) + fp16 dual-scatter with 16B stores.
// conv blocks: W fp32->fp16 slice (8 float4 each) + out-zero slice.
__global__ void __launch_bounds__(256)
prep_kernel(const float* __restrict__ x,
            const float4* __restrict__ W,
            const float* __restrict__ Wg,
            const float* __restrict__ bg,
            float4* __restrict__ out) {
    int bid = blockIdx.x;
    int tid = threadIdx.x;

    if (bid >= GATE_BLOCKS) {
        int cid = bid - GATE_BLOCKS;
        // W convert: 8,388,608 float4 over CONV_BLOCKS blocks (8 each)
        {
            uint2* dst = (uint2*)g_wh;
            size_t base = (size_t)cid * 2048 + tid;
#pragma unroll
            for (int i = 0; i < 8; i++) {
                size_t idx = base + (size_t)i * 256;
                float4 v = W[idx];
                dst[idx] = make_uint2(pack_h2(v.x, v.y), pack_h2(v.z, v.w));
            }
        }
        // zero out: 4,194,304 float4 over CONV_BLOCKS blocks (4 each)
        {
            float4 z = make_float4(0.f, 0.f, 0.f, 0.f);
            size_t base = (size_t)cid * 1024 + tid;
#pragma unroll
            for (int i = 0; i < 4; i++)
                out[base + (size_t)i * 256] = z;
        }
        return;
    }

    int wid  = tid >> 5;
    int lane = tid & 31;
    int tok  = bid * 8 + wid;

    const float* xr = x + (size_t)tok * DIM;
    float acc[NEXP];
#pragma unroll
    for (int e = 0; e < NEXP; e++) acc[e] = 0.f;
    for (int i = lane; i < DIM; i += 32) {
        float xv = xr[i];
#pragma unroll
        for (int e = 0; e < NEXP; e++)
            acc[e] = fmaf(xv, Wg[e * DIM + i], acc[e]);
    }
#pragma unroll
    for (int off = 16; off; off >>= 1)
#pragma unroll
        for (int e = 0; e < NEXP; e++)
            acc[e] += __shfl_xor_sync(0xffffffffu, acc[e], off);

    int i0 = 0, i1 = 0, p0 = 0, p1 = 0;
    if (lane == 0) {
        float m = -3.4e38f;
#pragma unroll
        for (int e = 0; e < NEXP; e++) { acc[e] += bg[e]; m = fmaxf(m, acc[e]); }
        float p[NEXP], s = 0.f;
#pragma unroll
        for (int e = 0; e < NEXP; e++) { p[e] = expf(acc[e] - m); s += p[e]; }
        i0 = 0;
#pragma unroll
        for (int e = 1; e < NEXP; e++) if (p[e] > p[i0]) i0 = e;
        i1 = (i0 == 0) ? 1 : 0;
#pragma unroll
        for (int e = 0; e < NEXP; e++)
            if (e != i0 && p[e] > p[i1]) i1 = e;

        float inv = 1.f / s;
        p0 = atomicAdd(&g_count[i0], 1);
        p1 = atomicAdd(&g_count[i1], 1);
        g_tok[i0 * NTOK + p0] = tok;  g_wt[i0 * NTOK + p0] = p[i0] * inv;
        g_tok[i1 * NTOK + p1] = tok;  g_wt[i1 * NTOK + p1] = p[i1] * inv;
    }
    i0 = __shfl_sync(0xffffffffu, i0, 0);
    i1 = __shfl_sync(0xffffffffu, i1, 0);
    p0 = __shfl_sync(0xffffffffu, p0, 0);
    p1 = __shfl_sync(0xffffffffu, p1, 0);

    // dual scatter of fp16 row, 16B stores (DIM/8 = 256 uint4 per row)
    const float4* src = (const float4*)xr;
    uint4* d0 = (uint4*)(g_xh + ((size_t)i0 * NTOK + p0) * DIM);
    uint4* d1 = (uint4*)(g_xh + ((size_t)i1 * NTOK + p1) * DIM);
    for (int i = lane; i < DIM / 8; i += 32) {
        float4 va = src[2 * i];
        float4 vb = src[2 * i + 1];
        uint4 h = make_uint4(pack_h2(va.x, va.y), pack_h2(va.z, va.w),
                             pack_h2(vb.x, vb.y), pack_h2(vb.z, vb.w));
        d0[i] = h;
        d1[i] = h;
    }
}

// ---------------- kernel 2: FP16 mma.sync grouped GEMM (R9 exact) ----------
// 256 thr, warps 4(M)x2(N), warp tile 32x64.  A frags double-buffered,
// B pairs JIT-rotated, 3-stage cp.async, one barrier per k-tile,
// atomic epilogue, 2 CTAs/SM.
__global__ void __launch_bounds__(256, 2)
moe_mma_gemm(const float* __restrict__ bias, float* __restrict__ out) {
    int bx = blockIdx.x;

    // derive (expert, row-tile) from counts
    int e = -1, r0 = 0, nt = 0;
#pragma unroll
    for (int i = 0; i < NEXP; i++) {
        int t = (g_count[i] + BM - 1) / BM;
        if (e < 0 && bx < nt + t) { e = i; r0 = (bx - nt) * BM; }
        nt += t;
    }
    if (e < 0) return;
    int cnt = g_count[e];
    int n0  = blockIdx.y * BN;

    extern __shared__ char smem[];
    uint32_t sbase = smem_u32(smem);

    int tid    = threadIdx.x;
    int lane   = tid & 31;
    int wid    = tid >> 5;
    int warp_m = wid & 3;
    int warp_n = wid >> 2;
    int fr     = lane >> 2;
    int fc     = lane & 3;

    int lrow = tid >> 1;
    int cgrp = (tid & 1) * 4;
    const __half* gA = g_xh + ((size_t)e * NTOK + r0 + lrow) * DIM + cgrp * 8;
    const __half* gB = g_wh + ((size_t)e * DIM + n0 + lrow) * DIM + cgrp * 8;
    uint32_t rowOff = lrow * 128;
    int      rSw    = lrow & 7;

    int mi  = lane >> 3;
    int r8  = lane & 7;
    int aCh = mi >> 1;
    uint32_t aBase[2];
    int      aSw[2];
#pragma unroll
    for (int tm = 0; tm < 2; tm++) {
        int r = warp_m * 32 + tm * 16 + (mi & 1) * 8 + r8;
        aBase[tm] = r * 128;
        aSw[tm]   = r & 7;
    }
    int bCh = mi & 1;
    uint32_t bBase[4];
    int      bSw[4];
#pragma unroll
    for (int p = 0; p < 4; p++) {
        int r = warp_n * 64 + (2 * p + (mi >> 1)) * 8 + r8;
        bBase[p] = r * 128;
        bSw[p]   = r & 7;
    }

    float acc[2][8][4];
#pragma unroll
    for (int i = 0; i < 2; i++)
#pragma unroll
        for (int j = 0; j < 8; j++)
#pragma unroll
            for (int k = 0; k < 4; k++) acc[i][j][k] = 0.f;

    auto load_stage = [&](int s, int kt) {
        uint32_t da = sbase + s * STAGE_BYTES + rowOff;
        uint32_t db = sbase + (STAGES + s) * STAGE_BYTES + rowOff;
        const __half* pa = gA + kt * BK;
        const __half* pb = gB + kt * BK;
#pragma unroll
        for (int c = 0; c < 4; c++) {
            uint32_t pc = (uint32_t)((cgrp + c) ^ rSw) << 4;
            CP16(da + pc, pa + c * 8);
            CP16(db + pc, pb + c * 8);
        }
        CP_COMMIT();
    };

    // fragment buffers: A double (per k16 step), B 2-slot pair rotation
    uint32_t a[2][2][4], b[2][4];

    auto load_a = [&](int buf, int kk, uint32_t As) {
#pragma unroll
        for (int tm = 0; tm < 2; tm++) {
            uint32_t addr = As + aBase[tm] +
                            ((uint32_t)((kk * 2 + aCh) ^ aSw[tm]) << 4);
            LDSM4(a[buf][tm][0], a[buf][tm][1], a[buf][tm][2], a[buf][tm][3], addr);
        }
    };
    auto load_b = [&](int buf, int kk, int p, uint32_t Bs) {
        uint32_t addr = Bs + bBase[p] +
                        ((uint32_t)((kk * 2 + bCh) ^ bSw[p]) << 4);
        LDSM4(b[buf][0], b[buf][1], b[buf][2], b[buf][3], addr);
    };

#pragma unroll
    for (int s = 0; s < STAGES - 1; s++) load_stage(s, s);

#pragma unroll 1
    for (int kt = 0; kt < KITERS; kt++) {
        if (kt < KITERS - 1) { CP_WAIT1(); } else { CP_WAIT0(); }
        __syncthreads();   // prior-iter reads done; stage kt resident

        uint32_t As = sbase + (kt % STAGES) * STAGE_BYTES;
        uint32_t Bs = sbase + (STAGES + (kt % STAGES)) * STAGE_BYTES;

        load_a(0, 0, As);
        load_b(0, 0, 0, Bs);

        int kp = kt + STAGES - 1;
        if (kp < KITERS) load_stage(kp % STAGES, kp);

#pragma unroll
        for (int j = 0; j < BK / 16; j++) {
            int cur = j & 1;
            if (j < BK / 16 - 1) load_a(cur ^ 1, j + 1, As);
#pragma unroll
            for (int p = 0; p < 4; p++) {
                int pb = p & 1;
                if (p < 3)                load_b(pb ^ 1, j,     p + 1, Bs);
                else if (j < BK / 16 - 1) load_b(pb ^ 1, j + 1, 0,     Bs);
#pragma unroll
                for (int tm = 0; tm < 2; tm++) {
                    mma_f16(acc[tm][2 * p],     a[cur][tm], &b[pb][0]);
                    mma_f16(acc[tm][2 * p + 1], a[cur][tm], &b[pb][2]);
                }
            }
        }
    }

    // epilogue: bias + relu + gate weight -> atomicAdd into out
    int c2 = 2 * fc;
    float2 bv[8];
#pragma unroll
    for (int tn = 0; tn < 8; tn++) {
        const float* bp = bias + (size_t)e * DIM + n0 + warp_n * 64 + tn * 8 + c2;
        bv[tn] = make_float2(__ldg(bp), __ldg(bp + 1));
    }
#pragma unroll
    for (int tm = 0; tm < 2; tm++) {
#pragma unroll
        for (int half = 0; half < 2; half++) {
            int row = warp_m * 32 + tm * 16 + half * 8 + fr;
            int idx = r0 + row;
            if (idx >= cnt) continue;
            int   tok = g_tok[e * NTOK + idx];
            float wgt = g_wt [e * NTOK + idx];
            float* orow = out + (size_t)tok * DIM + n0 + warp_n * 64;
#pragma unroll
            for (int tn = 0; tn < 8; tn++) {
                float v0 = fmaxf(acc[tm][tn][half * 2 + 0] + bv[tn].x, 0.f) * wgt;
                float v1 = fmaxf(acc[tm][tn][half * 2 + 1] + bv[tn].y, 0.f) * wgt;
                atomicAdd(orow + tn * 8 + c2,     v0);
                atomicAdd(orow + tn * 8 + c2 + 1, v1);
            }
        }
    }
}

// ---------------- launch ----------------
extern "C" void kernel_launch(void* const* d_in, const int* in_sizes, int n_in,
                              void* d_out, int out_size) {
    const float* x  = (const float*)d_in[0];
    const float* W  = (const float*)d_in[1];
    const float* b  = (const float*)d_in[2];
    const float* Wg = (const float*)d_in[3];
    const float* bg = (const float*)d_in[4];
    float* out = (float*)d_out;
    (void)in_sizes; (void)n_in; (void)out_size;

    cudaFuncSetAttribute(moe_mma_gemm, cudaFuncAttributeMaxDynamicSharedMemorySize, SMEM_TOTAL);

    init_kernel<<<1, 32>>>();
    prep_kernel<<<PREP_BLOCKS, 256>>>(x, (const float4*)W, Wg, bg, (float4*)out);
    moe_mma_gemm<<<dim3(GRID_ROWTILES, DIM / BN), 256, SMEM_TOTAL>>>(b, out);
}

// round 17
// speedup vs baseline: 1.0799x; 1.0023x over previous
#include <cuda_runtime.h>
#include <cuda_fp16.h>
#include <cstdint>

#define NTOK 8192
#define DIM  2048
#define NEXP 8
#define TOPK 2

#define BM 128
#define BN 128
#define BK 64                          // halves per k-iter
#define STAGES 3
#define KITERS (DIM / BK)              // 32

#define GRID_ROWTILES 136
#define GRID_TOTAL (GRID_ROWTILES * (DIM / BN))   // 2176 blocks, fixed

#define STAGE_BYTES (BM * BK * 2)      // 16384
#define SMEM_TOTAL  (2 * STAGES * STAGE_BYTES)  // 98304

#define GATE_BLOCKS 1024               // 8 warps/block, 1 token/warp
#define CONV_BLOCKS 4096               // W-convert + out-zero slices
#define PREP_BLOCKS (GATE_BLOCKS + CONV_BLOCKS)

// ---------------- device globals (zero-initialized at module load; the GEMM
// ticket-clears them at the end of every run, so each launch sees zeros) -----
__device__ int    g_count[NEXP];
__device__ int    g_done;
__device__ int    g_tok[NEXP * NTOK];
__device__ float  g_wt [NEXP * NTOK];
__device__ __half g_xh[(size_t)NEXP * NTOK * DIM];   // per-expert padded fp16 A
__device__ __half g_wh[(size_t)NEXP * DIM * DIM];    // fp16 W

// ---------------- helpers ----------------
__device__ __forceinline__ uint32_t smem_u32(const void* p) {
    uint32_t a;
    asm("{ .reg .u64 t; cvta.to.shared.u64 t, %1; cvt.u32.u64 %0, t; }" : "=r"(a) : "l"(p));
    return a;
}
#define CP16(dst, src) \
    asm volatile("cp.async.cg.shared.global [%0], [%1], 16;" :: "r"(dst), "l"(src) : "memory")
#define CP_COMMIT() asm volatile("cp.async.commit_group;" ::: "memory")
#define CP_WAIT1()  asm volatile("cp.async.wait_group 1;" ::: "memory")
#define CP_WAIT0()  asm volatile("cp.async.wait_group 0;" ::: "memory")

#define LDSM4(r0, r1, r2, r3, addr) \
    asm volatile("ldmatrix.sync.aligned.m8n8.x4.shared.b16 {%0,%1,%2,%3}, [%4];" \
        : "=r"(r0), "=r"(r1), "=r"(r2), "=r"(r3) : "r"(addr))

__device__ __forceinline__ void mma_f16(float* d, const uint32_t* a, const uint32_t* b) {
    asm volatile(
        "mma.sync.aligned.m16n8k16.row.col.f32.f16.f16.f32 "
        "{%0,%1,%2,%3}, {%4,%5,%6,%7}, {%8,%9}, {%0,%1,%2,%3};"
        : "+f"(d[0]), "+f"(d[1]), "+f"(d[2]), "+f"(d[3])
        : "r"(a[0]), "r"(a[1]), "r"(a[2]), "r"(a[3]), "r"(b[0]), "r"(b[1]));
}

__device__ __forceinline__ uint32_t pack_h2(float x, float y) {
    __half2 h = __floats2half2_rn(x, y);
    return *(uint32_t*)&h;
}

// ---------------- kernel 1: fused prep ----------------
// gate blocks: gating (1 warp/token) + fp16 dual-scatter with 16B stores.
// conv blocks: W fp32->fp16 slice (8 float4 each) + out-zero slice.
__global__ void __launch_bounds__(256)
prep_kernel(const float* __restrict__ x,
            const float4* __restrict__ W,
            const float* __restrict__ Wg,
            const float* __restrict__ bg,
            float4* __restrict__ out) {
    int bid = blockIdx.x;
    int tid = threadIdx.x;

    if (bid >= GATE_BLOCKS) {
        int cid = bid - GATE_BLOCKS;
        // W convert: 8,388,608 float4 over CONV_BLOCKS blocks (8 each)
        {
            uint2* dst = (uint2*)g_wh;
            size_t base = (size_t)cid * 2048 + tid;
#pragma unroll
            for (int i = 0; i < 8; i++) {
                size_t idx = base + (size_t)i * 256;
                float4 v = W[idx];
                dst[idx] = make_uint2(pack_h2(v.x, v.y), pack_h2(v.z, v.w));
            }
        }
        // zero out: 4,194,304 float4 over CONV_BLOCKS blocks (4 each)
        {
            float4 z = make_float4(0.f, 0.f, 0.f, 0.f);
            size_t base = (size_t)cid * 1024 + tid;
#pragma unroll
            for (int i = 0; i < 4; i++)
                out[base + (size_t)i * 256] = z;
        }
        return;
    }

    int wid  = tid >> 5;
    int lane = tid & 31;
    int tok  = bid * 8 + wid;

    const float* xr = x + (size_t)tok * DIM;
    float acc[NEXP];
#pragma unroll
    for (int e = 0; e < NEXP; e++) acc[e] = 0.f;
    for (int i = lane; i < DIM; i += 32) {
        float xv = xr[i];
#pragma unroll
        for (int e = 0; e < NEXP; e++)
            acc[e] = fmaf(xv, Wg[e * DIM + i], acc[e]);
    }
#pragma unroll
    for (int off = 16; off; off >>= 1)
#pragma unroll
        for (int e = 0; e < NEXP; e++)
            acc[e] += __shfl_xor_sync(0xffffffffu, acc[e], off);

    int i0 = 0, i1 = 0, p0 = 0, p1 = 0;
    if (lane == 0) {
        float m = -3.4e38f;
#pragma unroll
        for (int e = 0; e < NEXP; e++) { acc[e] += bg[e]; m = fmaxf(m, acc[e]); }
        float p[NEXP], s = 0.f;
#pragma unroll
        for (int e = 0; e < NEXP; e++) { p[e] = expf(acc[e] - m); s += p[e]; }
        i0 = 0;
#pragma unroll
        for (int e = 1; e < NEXP; e++) if (p[e] > p[i0]) i0 = e;
        i1 = (i0 == 0) ? 1 : 0;
#pragma unroll
        for (int e = 0; e < NEXP; e++)
            if (e != i0 && p[e] > p[i1]) i1 = e;

        float inv = 1.f / s;
        p0 = atomicAdd(&g_count[i0], 1);
        p1 = atomicAdd(&g_count[i1], 1);
        g_tok[i0 * NTOK + p0] = tok;  g_wt[i0 * NTOK + p0] = p[i0] * inv;
        g_tok[i1 * NTOK + p1] = tok;  g_wt[i1 * NTOK + p1] = p[i1] * inv;
    }
    i0 = __shfl_sync(0xffffffffu, i0, 0);
    i1 = __shfl_sync(0xffffffffu, i1, 0);
    p0 = __shfl_sync(0xffffffffu, p0, 0);
    p1 = __shfl_sync(0xffffffffu, p1, 0);

    // dual scatter of fp16 row, 16B stores (DIM/8 = 256 uint4 per row)
    const float4* src = (const float4*)xr;
    uint4* d0 = (uint4*)(g_xh + ((size_t)i0 * NTOK + p0) * DIM);
    uint4* d1 = (uint4*)(g_xh + ((size_t)i1 * NTOK + p1) * DIM);
    for (int i = lane; i < DIM / 8; i += 32) {
        float4 va = src[2 * i];
        float4 vb = src[2 * i + 1];
        uint4 h = make_uint4(pack_h2(va.x, va.y), pack_h2(va.z, va.w),
                             pack_h2(vb.x, vb.y), pack_h2(vb.z, vb.w));
        d0[i] = h;
        d1[i] = h;
    }
}

// ---------------- kernel 2: FP16 mma.sync grouped GEMM (R9 mainloop) -------
// 256 thr, warps 4(M)x2(N), warp tile 32x64.  A frags double-buffered,
// B pairs JIT-rotated, 3-stage cp.async, one barrier per k-tile,
// atomic epilogue, 2 CTAs/SM.  Last-finishing block (ticket) resets
// g_count/g_done to module-load state for the next graph replay.
__global__ void __launch_bounds__(256, 2)
moe_mma_gemm(const float* __restrict__ bias, float* __restrict__ out) {
    int bx = blockIdx.x;
    int tid = threadIdx.x;

    // derive (expert, row-tile) from counts
    int e = -1, r0 = 0, nt = 0;
#pragma unroll
    for (int i = 0; i < NEXP; i++) {
        int t = (g_count[i] + BM - 1) / BM;
        if (e < 0 && bx < nt + t) { e = i; r0 = (bx - nt) * BM; }
        nt += t;
    }
    if (e < 0) {
        // still participate in the reset ticket
        if (tid == 0) {
            int v = atomicAdd(&g_done, 1);
            if (v == GRID_TOTAL - 1) {
#pragma unroll
                for (int i = 0; i < NEXP; i++) g_count[i] = 0;
                g_done = 0;
            }
        }
        return;
    }
    int cnt = g_count[e];
    int n0  = blockIdx.y * BN;

    extern __shared__ char smem[];
    uint32_t sbase = smem_u32(smem);

    int lane   = tid & 31;
    int wid    = tid >> 5;
    int warp_m = wid & 3;
    int warp_n = wid >> 2;
    int fr     = lane >> 2;
    int fc     = lane & 3;

    int lrow = tid >> 1;
    int cgrp = (tid & 1) * 4;
    const __half* gA = g_xh + ((size_t)e * NTOK + r0 + lrow) * DIM + cgrp * 8;
    const __half* gB = g_wh + ((size_t)e * DIM + n0 + lrow) * DIM + cgrp * 8;
    uint32_t rowOff = lrow * 128;
    int      rSw    = lrow & 7;

    int mi  = lane >> 3;
    int r8  = lane & 7;
    int aCh = mi >> 1;
    uint32_t aBase[2];
    int      aSw[2];
#pragma unroll
    for (int tm = 0; tm < 2; tm++) {
        int r = warp_m * 32 + tm * 16 + (mi & 1) * 8 + r8;
        aBase[tm] = r * 128;
        aSw[tm]   = r & 7;
    }
    int bCh = mi & 1;
    uint32_t bBase[4];
    int      bSw[4];
#pragma unroll
    for (int p = 0; p < 4; p++) {
        int r = warp_n * 64 + (2 * p + (mi >> 1)) * 8 + r8;
        bBase[p] = r * 128;
        bSw[p]   = r & 7;
    }

    float acc[2][8][4];
#pragma unroll
    for (int i = 0; i < 2; i++)
#pragma unroll
        for (int j = 0; j < 8; j++)
#pragma unroll
            for (int k = 0; k < 4; k++) acc[i][j][k] = 0.f;

    auto load_stage = [&](int s, int kt) {
        uint32_t da = sbase + s * STAGE_BYTES + rowOff;
        uint32_t db = sbase + (STAGES + s) * STAGE_BYTES + rowOff;
        const __half* pa = gA + kt * BK;
        const __half* pb = gB + kt * BK;
#pragma unroll
        for (int c = 0; c < 4; c++) {
            uint32_t pc = (uint32_t)((cgrp + c) ^ rSw) << 4;
            CP16(da + pc, pa + c * 8);
            CP16(db + pc, pb + c * 8);
        }
        CP_COMMIT();
    };

    // fragment buffers: A double (per k16 step), B 2-slot pair rotation
    uint32_t a[2][2][4], b[2][4];

    auto load_a = [&](int buf, int kk, uint32_t As) {
#pragma unroll
        for (int tm = 0; tm < 2; tm++) {
            uint32_t addr = As + aBase[tm] +
                            ((uint32_t)((kk * 2 + aCh) ^ aSw[tm]) << 4);
            LDSM4(a[buf][tm][0], a[buf][tm][1], a[buf][tm][2], a[buf][tm][3], addr);
        }
    };
    auto load_b = [&](int buf, int kk, int p, uint32_t Bs) {
        uint32_t addr = Bs + bBase[p] +
                        ((uint32_t)((kk * 2 + bCh) ^ bSw[p]) << 4);
        LDSM4(b[buf][0], b[buf][1], b[buf][2], b[buf][3], addr);
    };

#pragma unroll
    for (int s = 0; s < STAGES - 1; s++) load_stage(s, s);

#pragma unroll 1
    for (int kt = 0; kt < KITERS; kt++) {
        if (kt < KITERS - 1) { CP_WAIT1(); } else { CP_WAIT0(); }
        __syncthreads();   // prior-iter reads done; stage kt resident

        uint32_t As = sbase + (kt % STAGES) * STAGE_BYTES;
        uint32_t Bs = sbase + (STAGES + (kt % STAGES)) * STAGE_BYTES;

        load_a(0, 0, As);
        load_b(0, 0, 0, Bs);

        int kp = kt + STAGES - 1;
        if (kp < KITERS) load_stage(kp % STAGES, kp);

#pragma unroll
        for (int j = 0; j < BK / 16; j++) {
            int cur = j & 1;
            if (j < BK / 16 - 1) load_a(cur ^ 1, j + 1, As);
#pragma unroll
            for (int p = 0; p < 4; p++) {
                int pb = p & 1;
                if (p < 3)                load_b(pb ^ 1, j,     p + 1, Bs);
                else if (j < BK / 16 - 1) load_b(pb ^ 1, j + 1, 0,     Bs);
#pragma unroll
                for (int tm = 0; tm < 2; tm++) {
                    mma_f16(acc[tm][2 * p],     a[cur][tm], &b[pb][0]);
                    mma_f16(acc[tm][2 * p + 1], a[cur][tm], &b[pb][2]);
                }
            }
        }
    }

    // epilogue: bias + relu + gate weight -> atomicAdd into out
    int c2 = 2 * fc;
    float2 bv[8];
#pragma unroll
    for (int tn = 0; tn < 8; tn++) {
        const float* bp = bias + (size_t)e * DIM + n0 + warp_n * 64 + tn * 8 + c2;
        bv[tn] = make_float2(__ldg(bp), __ldg(bp + 1));
    }
#pragma unroll
    for (int tm = 0; tm < 2; tm++) {
#pragma unroll
        for (int half = 0; half < 2; half++) {
            int row = warp_m * 32 + tm * 16 + half * 8 + fr;
            int idx = r0 + row;
            if (idx >= cnt) continue;
            int   tok = g_tok[e * NTOK + idx];
            float wgt = g_wt [e * NTOK + idx];
            float* orow = out + (size_t)tok * DIM + n0 + warp_n * 64;
#pragma unroll
            for (int tn = 0; tn < 8; tn++) {
                float v0 = fmaxf(acc[tm][tn][half * 2 + 0] + bv[tn].x, 0.f) * wgt;
                float v1 = fmaxf(acc[tm][tn][half * 2 + 1] + bv[tn].y, 0.f) * wgt;
                atomicAdd(orow + tn * 8 + c2,     v0);
                atomicAdd(orow + tn * 8 + c2 + 1, v1);
            }
        }
    }

    // reset ticket: after ALL blocks' g_count reads + work are done,
    // the last block restores counters to module-load state (zeros).
    __syncthreads();
    if (tid == 0) {
        int v = atomicAdd(&g_done, 1);
        if (v == GRID_TOTAL - 1) {
#pragma unroll
            for (int i = 0; i < NEXP; i++) g_count[i] = 0;
            g_done = 0;
        }
    }
}

// ---------------- launch ----------------
extern "C" void kernel_launch(void* const* d_in, const int* in_sizes, int n_in,
                              void* d_out, int out_size) {
    const float* x  = (const float*)d_in[0];
    const float* W  = (const float*)d_in[1];
    const float* b  = (const float*)d_in[2];
    const float* Wg = (const float*)d_in[3];
    const float* bg = (const float*)d_in[4];
    float* out = (float*)d_out;
    (void)in_sizes; (void)n_in; (void)out_size;

    cudaFuncSetAttribute(moe_mma_gemm, cudaFuncAttributeMaxDynamicSharedMemorySize, SMEM_TOTAL);

    prep_kernel<<<PREP_BLOCKS, 256>>>(x, (const float4*)W, Wg, bg, (float4*)out);
    moe_mma_gemm<<<dim3(GRID_ROWTILES, DIM / BN), 256, SMEM_TOTAL>>>(b, out);
}